// round 1
// baseline (speedup 1.0000x reference)
#include <cuda_runtime.h>
#include <math.h>
#include <float.h>

#define BB   2
#define LL   2048
#define HH   8
#define EE   32
#define SS   2048
#define DD   32

#define TM   64      // query rows per CTA
#define TN   32      // key cols per tile
#define NT   256     // threads per CTA (8 warps)

// padded smem strides (floats) to keep float4 alignment + limit bank conflicts
#define QP_S 36
#define KP_S 36
#define VT_S 36

__global__ void __launch_bounds__(NT)
gauss_attn_kernel(const float* __restrict__ q,
                  const float* __restrict__ k,
                  const float* __restrict__ v,
                  float* __restrict__ out)
{
    __shared__ float Qs [TM][EE];    // q * (inv*scale)  (broadcast reads)
    __shared__ float Qps[TM][QP_S];  // scrambled q' * inv
    __shared__ float q2s[TM];        // ||q'||^2
    __shared__ float Ks [TN][KP_S];  // k * inv
    __shared__ float Kps[TN][KP_S];  // scrambled k' * inv
    __shared__ float VsT[DD][VT_S];  // V tile transposed: VsT[d][s]
    __shared__ float Ps [TM][TN];    // softmax probabilities

    const int bh   = blockIdx.y;          // b*8 + h
    const int b    = bh >> 3;
    const int h    = bh & 7;
    const int l0   = blockIdx.x * TM;
    const int tid  = threadIdx.x;
    const int w    = tid >> 5;
    const int lane = tid & 31;

    const float inv    = 0.17677669529663687f;   // 1/sqrt(32)
    const float qscale = inv * inv;              // fold softmax scale into Q

    // ---- load Q tile (both the direct rows and the scrambled rows) ----
    // 64 rows x 8 float4-chunks = 512 float4; 2 per thread
    #pragma unroll
    for (int j = 0; j < 2; j++) {
        int i  = tid + NT * j;          // 0..511
        int r  = i >> 3;                // row in tile
        int ec = i & 7;                 // float4 chunk
        int l  = l0 + r;

        const float4* src = (const float4*)(q + (((size_t)(b * LL + l) * HH + h) * EE)) + ec;
        float4 val = *src;
        val.x *= qscale; val.y *= qscale; val.z *= qscale; val.w *= qscale;
        *(float4*)(&Qs[r][ec * 4]) = val;

        int lq = h * 256 + (l >> 3);
        int hq = l & 7;
        const float4* srcp = (const float4*)(q + (((size_t)(b * LL + lq) * HH + hq) * EE)) + ec;
        float4 vp = *srcp;
        vp.x *= inv; vp.y *= inv; vp.z *= inv; vp.w *= inv;
        *(float4*)(&Qps[r][ec * 4]) = vp;
    }
    __syncthreads();

    if (tid < TM) {
        float s = 0.f;
        #pragma unroll
        for (int e = 0; e < EE; e++) { float t = Qps[tid][e]; s += t * t; }
        q2s[tid] = s;
    }
    __syncthreads();

    // per-warp row state
    float q2r[8];
    #pragma unroll
    for (int i = 0; i < 8; i++) q2r[i] = q2s[w * 8 + i];

    float mrow[8], lrow[8], oacc[8];
    #pragma unroll
    for (int i = 0; i < 8; i++) { mrow[i] = -1e30f; lrow[i] = 0.f; oacc[i] = 0.f; }

    const int myRowMax = l0 + w * 8 + 7;
    const int nTiles   = (l0 + TM) / TN;   // s0 ranges over [0, l0+TM)

    for (int t = 0; t < nTiles; t++) {
        const int s0 = t * TN;

        // ---- load K / K' tile (1 float4 each per thread) ----
        {
            int r  = tid >> 3;
            int ec = tid & 7;
            int s  = s0 + r;

            float4 kv = *((const float4*)(k + (((size_t)(b * SS + s) * HH + h) * EE)) + ec);
            kv.x *= inv; kv.y *= inv; kv.z *= inv; kv.w *= inv;
            *(float4*)(&Ks[r][ec * 4]) = kv;

            int sk = h * 256 + (s >> 3);
            int hk = s & 7;
            float4 kp = *((const float4*)(k + (((size_t)(b * SS + sk) * HH + hk) * EE)) + ec);
            kp.x *= inv; kp.y *= inv; kp.z *= inv; kp.w *= inv;
            *(float4*)(&Kps[r][ec * 4]) = kp;
        }
        // ---- load V tile, transposed ----
        #pragma unroll
        for (int j = 0; j < 4; j++) {
            int i = tid + NT * j;       // 0..1023
            int s = i >> 5;
            int d = i & 31;
            VsT[d][s] = v[(((size_t)(b * SS + (s0 + s))) * HH + h) * DD + d];
        }
        __syncthreads();

        if (s0 <= myRowMax) {
            // ---- pass 1: logits (lane = column s0+lane, 8 rows) ----
            float acc[8], accp[8];
            #pragma unroll
            for (int i = 0; i < 8; i++) { acc[i] = 0.f; accp[i] = 0.f; }
            float k2 = 0.f;

            #pragma unroll
            for (int ec = 0; ec < 8; ec++) {
                float4 kf = *(const float4*)&Ks [lane][ec * 4];
                float4 kp = *(const float4*)&Kps[lane][ec * 4];
                k2 += kp.x * kp.x + kp.y * kp.y + kp.z * kp.z + kp.w * kp.w;
                #pragma unroll
                for (int i = 0; i < 8; i++) {
                    float4 qf = *(const float4*)&Qs [w * 8 + i][ec * 4];
                    float4 qp = *(const float4*)&Qps[w * 8 + i][ec * 4];
                    acc [i] += qf.x * kf.x + qf.y * kf.y + qf.z * kf.z + qf.w * kf.w;
                    accp[i] += qp.x * kp.x + qp.y * kp.y + qp.z * kp.z + qp.w * kp.w;
                }
            }

            // ---- online softmax update ----
            float alpha[8];
            const int lbase = l0 + w * 8;
            const int sg    = s0 + lane;
            #pragma unroll
            for (int i = 0; i < 8; i++) {
                int lg = lbase + i;
                float logit;
                if (sg <= lg) {
                    float sq = q2r[i] + k2 - 2.f * accp[i];
                    sq = fmaxf(sq, 0.f);
                    logit = acc[i] * __expf(-sq);   // scale already folded into Qs
                } else {
                    logit = -1e30f;
                }
                float tmax = logit;
                #pragma unroll
                for (int off = 16; off > 0; off >>= 1)
                    tmax = fmaxf(tmax, __shfl_xor_sync(0xffffffffu, tmax, off));
                float mnew = fmaxf(mrow[i], tmax);
                float a    = __expf(mrow[i] - mnew);
                float p    = __expf(logit - mnew);
                float rs   = p;
                #pragma unroll
                for (int off = 16; off > 0; off >>= 1)
                    rs += __shfl_xor_sync(0xffffffffu, rs, off);
                lrow[i]  = lrow[i] * a + rs;
                mrow[i]  = mnew;
                alpha[i] = a;
                Ps[w * 8 + i][lane] = p;
            }
            __syncwarp();

            // ---- pass 2: O += P * V  (lane = d) ----
            #pragma unroll
            for (int i = 0; i < 8; i++) {
                float o = oacc[i] * alpha[i];
                #pragma unroll
                for (int ec = 0; ec < 8; ec++) {
                    float4 pf = *(const float4*)&Ps [w * 8 + i][ec * 4];
                    float4 vf = *(const float4*)&VsT[lane][ec * 4];
                    o += pf.x * vf.x + pf.y * vf.y + pf.z * vf.z + pf.w * vf.w;
                }
                oacc[i] = o;
            }
        }
        __syncthreads();
    }

    // ---- epilogue: normalize and write out[b, l, h, d] ----
    #pragma unroll
    for (int i = 0; i < 8; i++) {
        int l = l0 + w * 8 + i;
        out[(((size_t)(b * LL + l)) * HH + h) * DD + lane] = oacc[i] / lrow[i];
    }
}

extern "C" void kernel_launch(void* const* d_in, const int* in_sizes, int n_in,
                              void* d_out, int out_size)
{
    const float* q = (const float*)d_in[0];
    const float* k = (const float*)d_in[1];
    const float* v = (const float*)d_in[2];
    float* out = (float*)d_out;

    dim3 grid(LL / TM, BB * HH);
    gauss_attn_kernel<<<grid, NT>>>(q, k, v, out);
}

// round 2
// speedup vs baseline: 1.5709x; 1.5709x over previous
#include <cuda_runtime.h>

#define BB 2
#define LL 2048
#define HH 8
#define EE 32
#define SS 2048
#define DD 32

#define TM 64      // query rows per CTA
#define TN 64      // key cols per tile
#define NT 256     // threads (8 warps x 8 rows each)

struct SmemLayout {
    float Qs [TM][EE];      // q * inv^2 (scale folded)  — broadcast reads
    float Qps[TM][EE];      // scrambled q' * inv        — broadcast reads
    float q2s[TM];          // ||q'||^2
    float Ks [2][TN][EE];   // k * inv      (XOR-swizzled chunks)
    float Kps[2][TN][EE];   // k' * inv     (XOR-swizzled chunks)
    float Vs [2][TN][DD];   // V natural [s][d]
    float Ps [TM][TN];      // probabilities
};

__device__ __forceinline__ float dot4(float4 a, float4 b) {
    return a.x * b.x + a.y * b.y + a.z * b.z + a.w * b.w;
}

__global__ void __launch_bounds__(NT, 2)
gauss_attn_kernel(const float* __restrict__ qg,
                  const float* __restrict__ kg,
                  const float* __restrict__ vg,
                  float* __restrict__ outg)
{
    extern __shared__ char smem_raw[];
    SmemLayout& sm = *reinterpret_cast<SmemLayout*>(smem_raw);

    const int bh   = blockIdx.y;
    const int b    = bh >> 3;
    const int h    = bh & 7;
    const int l0   = blockIdx.x * TM;
    const int tid  = threadIdx.x;
    const int w    = tid >> 5;
    const int lane = tid & 31;

    const float inv = 0.17677669529663687f;   // 1/sqrt(32)
    const float qsc = inv * inv;              // fold softmax scale into Q

    // ---- prologue: load Q / Q' tiles, compute ||q'||^2 via intra-group shuffles ----
    #pragma unroll
    for (int j = 0; j < 2; j++) {
        int i = tid + NT * j;        // 0..511
        int r = i >> 3, c = i & 7;
        int l = l0 + r;
        float4 qv = *((const float4*)(qg + ((b * LL + l) * HH + h) * EE) + c);
        qv.x *= qsc; qv.y *= qsc; qv.z *= qsc; qv.w *= qsc;
        *(float4*)&sm.Qs[r][c << 2] = qv;

        int lq = h * 256 + (l >> 3), hq = l & 7;   // scrambled reshape index
        float4 qp = *((const float4*)(qg + ((b * LL + lq) * HH + hq) * EE) + c);
        qp.x *= inv; qp.y *= inv; qp.z *= inv; qp.w *= inv;
        *(float4*)&sm.Qps[r][c << 2] = qp;

        float part = dot4(qp, qp);
        part += __shfl_xor_sync(0xffffffffu, part, 1);
        part += __shfl_xor_sync(0xffffffffu, part, 2);
        part += __shfl_xor_sync(0xffffffffu, part, 4);
        if ((tid & 7) == 0) sm.q2s[r] = part;
    }

    // ---- load tile 0 into buffer 0 ----
    #pragma unroll
    for (int j = 0; j < 2; j++) {
        int i = tid + NT * j;
        int r = i >> 3, c = i & 7;
        int s = r;                                  // s0 = 0
        int cs = ((c ^ (r & 7)) << 2);              // XOR swizzle
        float4 kv = *((const float4*)(kg + ((b * SS + s) * HH + h) * EE) + c);
        kv.x *= inv; kv.y *= inv; kv.z *= inv; kv.w *= inv;
        *(float4*)&sm.Ks[0][r][cs] = kv;
        int sk = h * 256 + (s >> 3), hk = s & 7;
        float4 kp = *((const float4*)(kg + ((b * SS + sk) * HH + hk) * EE) + c);
        kp.x *= inv; kp.y *= inv; kp.z *= inv; kp.w *= inv;
        *(float4*)&sm.Kps[0][r][cs] = kp;
        *(float4*)&sm.Vs[0][r][c << 2] =
            *((const float4*)(vg + ((b * SS + s) * HH + h) * DD) + c);
    }
    __syncthreads();

    float q2r[8];
    #pragma unroll
    for (int i = 0; i < 8; i++) q2r[i] = sm.q2s[w * 8 + i];

    float oacc[8], lsum[8];
    #pragma unroll
    for (int i = 0; i < 8; i++) { oacc[i] = 0.f; lsum[i] = 0.f; }

    const int lbase = l0 + w * 8;
    const int nT    = blockIdx.x + 1;       // tiles cover s in [0, l0+64)

    for (int t = 0; t < nT; t++) {
        const int  cur  = t & 1;
        const int  s0   = t * TN;
        const bool pref = (t + 1 < nT);

        // ---- prefetch next tile into registers (latency overlapped with compute) ----
        float4 pk[2], pkp[2], pv[2];
        if (pref) {
            const int s0n = s0 + TN;
            #pragma unroll
            for (int j = 0; j < 2; j++) {
                int i = tid + NT * j;
                int r = i >> 3, c = i & 7;
                int s = s0n + r;
                pk[j] = *((const float4*)(kg + ((b * SS + s) * HH + h) * EE) + c);
                int sk = h * 256 + (s >> 3), hk = s & 7;
                pkp[j] = *((const float4*)(kg + ((b * SS + sk) * HH + hk) * EE) + c);
                pv[j]  = *((const float4*)(vg + ((b * SS + s) * HH + h) * DD) + c);
            }
        }

        if (s0 <= lbase + 7) {   // warp has unmasked work in this tile
            // ---- pass 1: two dot products per (row, col), cols = lane, lane+32 ----
            float d0[8], d1[8], c0[8], c1[8];
            #pragma unroll
            for (int i = 0; i < 8; i++) { d0[i] = d1[i] = c0[i] = c1[i] = 0.f; }
            float k2a = 0.f, k2b = 0.f;
            const int sw = lane & 7;
            #pragma unroll
            for (int c = 0; c < 8; c++) {
                const int cs = ((c ^ sw) << 2);     // de-swizzle -> original chunk c
                float4 kf0 = *(const float4*)&sm.Ks [cur][lane     ][cs];
                float4 kf1 = *(const float4*)&sm.Ks [cur][lane + 32][cs];
                float4 kp0 = *(const float4*)&sm.Kps[cur][lane     ][cs];
                float4 kp1 = *(const float4*)&sm.Kps[cur][lane + 32][cs];
                k2a += dot4(kp0, kp0);
                k2b += dot4(kp1, kp1);
                #pragma unroll
                for (int i = 0; i < 8; i++) {
                    float4 qf = *(const float4*)&sm.Qs [w * 8 + i][c << 2];
                    float4 qp = *(const float4*)&sm.Qps[w * 8 + i][c << 2];
                    d0[i] += dot4(qf, kf0);
                    d1[i] += dot4(qf, kf1);
                    c0[i] += dot4(qp, kp0);
                    c1[i] += dot4(qp, kp1);
                }
            }

            // ---- probabilities (no running max needed: logits are O(1)) ----
            const int sg0 = s0 + lane, sg1 = sg0 + 32;
            #pragma unroll
            for (int i = 0; i < 8; i++) {
                const int lg = lbase + i;
                float p0 = 0.f, p1 = 0.f;
                if (sg0 <= lg) {
                    float sq = fmaxf(q2r[i] + k2a - 2.f * c0[i], 0.f);
                    p0 = __expf(d0[i] * __expf(-sq));
                }
                if (sg1 <= lg) {
                    float sq = fmaxf(q2r[i] + k2b - 2.f * c1[i], 0.f);
                    p1 = __expf(d1[i] * __expf(-sq));
                }
                lsum[i] += p0 + p1;
                sm.Ps[w * 8 + i][lane]      = p0;
                sm.Ps[w * 8 + i][lane + 32] = p1;
            }
            __syncwarp();

            // ---- pass 2: O += P * V   (lane = d) ----
            #pragma unroll
            for (int half = 0; half < 2; half++) {
                float vr[32];
                #pragma unroll
                for (int s = 0; s < 32; s++)
                    vr[s] = sm.Vs[cur][half * 32 + s][lane];   // bank = lane, conflict-free
                #pragma unroll
                for (int i = 0; i < 8; i++) {
                    float o = 0.f;
                    #pragma unroll
                    for (int c = 0; c < 8; c++) {
                        float4 pf = *(const float4*)&sm.Ps[w * 8 + i][half * 32 + (c << 2)];
                        o += pf.x * vr[c * 4]     + pf.y * vr[c * 4 + 1]
                           + pf.z * vr[c * 4 + 2] + pf.w * vr[c * 4 + 3];
                    }
                    oacc[i] += o;
                }
            }
        }

        // ---- store prefetched tile into the other buffer ----
        if (pref) {
            const int nb = cur ^ 1;
            #pragma unroll
            for (int j = 0; j < 2; j++) {
                int i = tid + NT * j;
                int r = i >> 3, c = i & 7;
                int cs = ((c ^ (r & 7)) << 2);
                float4 kv = pk[j];
                kv.x *= inv; kv.y *= inv; kv.z *= inv; kv.w *= inv;
                *(float4*)&sm.Ks[nb][r][cs] = kv;
                float4 kp = pkp[j];
                kp.x *= inv; kp.y *= inv; kp.z *= inv; kp.w *= inv;
                *(float4*)&sm.Kps[nb][r][cs] = kp;
                *(float4*)&sm.Vs[nb][r][c << 2] = pv[j];
            }
        }
        __syncthreads();
    }

    // ---- epilogue: single cross-lane reduction of the softmax denominator ----
    #pragma unroll
    for (int i = 0; i < 8; i++) {
        float s = lsum[i];
        #pragma unroll
        for (int off = 16; off > 0; off >>= 1)
            s += __shfl_xor_sync(0xffffffffu, s, off);
        int l = lbase + i;
        outg[((b * LL + l) * HH + h) * DD + lane] = oacc[i] / s;
    }
}

extern "C" void kernel_launch(void* const* d_in, const int* in_sizes, int n_in,
                              void* d_out, int out_size)
{
    cudaFuncSetAttribute(gauss_attn_kernel,
                         cudaFuncAttributeMaxDynamicSharedMemorySize,
                         (int)sizeof(SmemLayout));
    dim3 grid(LL / TM, BB * HH);
    gauss_attn_kernel<<<grid, NT, sizeof(SmemLayout)>>>(
        (const float*)d_in[0], (const float*)d_in[1], (const float*)d_in[2],
        (float*)d_out);
}

// round 4
// speedup vs baseline: 3.7169x; 2.3660x over previous
#include <cuda_runtime.h>
#include <cuda_bf16.h>
#include <cstdint>

#define LLEN 2048
#define HH   8
#define EE   32
#define DD   32
#define NTHR 128
#define PAD  36        // f32 words per smem row (bank-conflict padding)

struct TileBuf {
    float K [64][PAD];
    float Kp[64][PAD];
    float V [64][PAD];
    float k2[64];
};
#define SMEM_BYTES (2 * (int)sizeof(TileBuf))

__device__ __forceinline__ uint32_t smem_u32(const void* p) {
    uint32_t a;
    asm("{ .reg .u64 t; cvta.to.shared.u64 t, %1; cvt.u32.u64 %0, t; }"
        : "=r"(a) : "l"(p));
    return a;
}
__device__ __forceinline__ void cp16(uint32_t dst, const void* src) {
    asm volatile("cp.async.cg.shared.global [%0], [%1], 16;"
                 :: "r"(dst), "l"(src) : "memory");
}
#define CP_COMMIT() asm volatile("cp.async.commit_group;" ::: "memory")
#define CP_WAIT0()  asm volatile("cp.async.wait_group 0;" ::: "memory")

// split (x,y) into packed bf16x2 hi and residual lo (x in low half = even col)
__device__ __forceinline__ void split2(float x, float y, uint32_t& hi, uint32_t& lo) {
    __nv_bfloat162 h = __floats2bfloat162_rn(x, y);
    float2 hf = __bfloat1622float2(h);
    __nv_bfloat162 l = __floats2bfloat162_rn(x - hf.x, y - hf.y);
    hi = *reinterpret_cast<uint32_t*>(&h);
    lo = *reinterpret_cast<uint32_t*>(&l);
}

__device__ __forceinline__ void mma16816(float4& d, const uint32_t* a,
                                         uint32_t b0, uint32_t b1) {
    asm volatile(
        "mma.sync.aligned.m16n8k16.row.col.f32.bf16.bf16.f32 "
        "{%0,%1,%2,%3}, {%4,%5,%6,%7}, {%8,%9}, {%0,%1,%2,%3};"
        : "+f"(d.x), "+f"(d.y), "+f"(d.z), "+f"(d.w)
        : "r"(a[0]), "r"(a[1]), "r"(a[2]), "r"(a[3]), "r"(b0), "r"(b1));
}

__device__ __forceinline__ void issue_tile(TileBuf* tb, const float* kg,
                                           const float* vg, int b, int h,
                                           int s0, int tid) {
    const int r = tid >> 1;
    const int half = tid & 1;
    const int sg = s0 + r;
    const float* ks  = kg + ((size_t)(b * LLEN + sg) * HH + h) * EE;
    const int sk = h * 256 + (sg >> 3), hk = sg & 7;      // scrambled reshape row
    const float* kps = kg + ((size_t)(b * LLEN + sk) * HH + hk) * EE;
    const float* vs  = vg + ((size_t)(b * LLEN + sg) * HH + h) * DD;
    #pragma unroll
    for (int m = 0; m < 4; m++) {
        const int c4 = half * 4 + m;
        cp16(smem_u32(&tb->K [r][c4 * 4]), ks  + c4 * 4);
        cp16(smem_u32(&tb->Kp[r][c4 * 4]), kps + c4 * 4);
        cp16(smem_u32(&tb->V [r][c4 * 4]), vs  + c4 * 4);
    }
}

__device__ __forceinline__ float pfun(float s, float c, float q2, float k2) {
    float sq = fmaxf(q2 + k2 - 2.f * c, 0.f);
    return __expf(s * __expf(-sq));
}

__global__ void __launch_bounds__(NTHR, 4)
gauss_attn_mma(const float* __restrict__ qg, const float* __restrict__ kg,
               const float* __restrict__ vg, float* __restrict__ outg)
{
    extern __shared__ TileBuf tiles[];     // [2]
    const int tid  = threadIdx.x;
    const int wid  = tid >> 5;
    const int lane = tid & 31;
    const int g    = lane >> 2;
    const int tg   = lane & 3;

    const int bx = blockIdx.x;
    const int lt = 31 - (bx >> 4);         // heavy diagonal tiles first
    const int bh = bx & 15;
    const int b  = bh >> 3, h = bh & 7;
    const int l0 = lt * 64;
    const int nT = lt + 1;

    const float inv2 = 0.03125f;                       // 1/32
    const float inv3 = 0.005524271728019903f;          // 32^-1.5

    const int r0g = l0 + wid * 16 + g;
    const int r1g = r0g + 8;

    // kick off tile 0 while we build Q fragments
    issue_tile(&tiles[0], kg, vg, b, h, 0, tid);
    CP_COMMIT();

    // ---- Q / Q' A-fragments (persist whole kernel), plus q2 ----
    uint32_t qAh[2][4], qAl[2][4], pAh_[2][4], pAl_[2][4];
    float q2r0 = 0.f, q2r1 = 0.f;
    #pragma unroll
    for (int kk = 0; kk < 2; kk++) {
        const float* p0 = qg + ((size_t)(b * LLEN + r0g) * HH + h) * EE + 16 * kk + 2 * tg;
        const float* p1 = qg + ((size_t)(b * LLEN + r1g) * HH + h) * EE + 16 * kk + 2 * tg;
        float2 a0 = *(const float2*)p0;
        float2 a1 = *(const float2*)p1;
        float2 a2 = *(const float2*)(p0 + 8);
        float2 a3 = *(const float2*)(p1 + 8);
        split2(a0.x * inv3, a0.y * inv3, qAh[kk][0], qAl[kk][0]);
        split2(a1.x * inv3, a1.y * inv3, qAh[kk][1], qAl[kk][1]);
        split2(a2.x * inv3, a2.y * inv3, qAh[kk][2], qAl[kk][2]);
        split2(a3.x * inv3, a3.y * inv3, qAh[kk][3], qAl[kk][3]);

        const int lq0 = h * 256 + (r0g >> 3), hq0 = r0g & 7;
        const int lq1 = h * 256 + (r1g >> 3), hq1 = r1g & 7;
        const float* s0p = qg + ((size_t)(b * LLEN + lq0) * HH + hq0) * EE + 16 * kk + 2 * tg;
        const float* s1p = qg + ((size_t)(b * LLEN + lq1) * HH + hq1) * EE + 16 * kk + 2 * tg;
        float2 b0 = *(const float2*)s0p;
        float2 b1 = *(const float2*)s1p;
        float2 b2 = *(const float2*)(s0p + 8);
        float2 b3 = *(const float2*)(s1p + 8);
        q2r0 += b0.x * b0.x + b0.y * b0.y + b2.x * b2.x + b2.y * b2.y;
        q2r1 += b1.x * b1.x + b1.y * b1.y + b3.x * b3.x + b3.y * b3.y;
        split2(b0.x * inv2, b0.y * inv2, pAh_[kk][0], pAl_[kk][0]);
        split2(b1.x * inv2, b1.y * inv2, pAh_[kk][1], pAl_[kk][1]);
        split2(b2.x * inv2, b2.y * inv2, pAh_[kk][2], pAl_[kk][2]);
        split2(b3.x * inv2, b3.y * inv2, pAh_[kk][3], pAl_[kk][3]);
    }
    q2r0 += __shfl_xor_sync(0xffffffffu, q2r0, 1);
    q2r0 += __shfl_xor_sync(0xffffffffu, q2r0, 2);
    q2r1 += __shfl_xor_sync(0xffffffffu, q2r1, 1);
    q2r1 += __shfl_xor_sync(0xffffffffu, q2r1, 2);
    q2r0 *= inv2;  q2r1 *= inv2;

    float4 O[4];
    #pragma unroll
    for (int i = 0; i < 4; i++) O[i] = make_float4(0.f, 0.f, 0.f, 0.f);
    float lsum0 = 0.f, lsum1 = 0.f;

    for (int t = 0; t < nT; t++) {
        const int cur = t & 1;
        CP_WAIT0();
        __syncthreads();
        if (t + 1 < nT) {
            issue_tile(&tiles[cur ^ 1], kg, vg, b, h, (t + 1) * 64, tid);
            CP_COMMIT();
        }
        // ---- k2 for this tile ----
        {
            const int s = tid >> 1, half = tid & 1;
            float acc = 0.f;
            #pragma unroll
            for (int e = 0; e < 16; e++) {
                float x = tiles[cur].Kp[s][half * 16 + e];
                acc += x * x;
            }
            acc += __shfl_xor_sync(0xffffffffu, acc, 1);
            if (half == 0) tiles[cur].k2[s] = acc * inv2;
        }
        __syncthreads();

        const int  s0    = t * 64;
        const bool maskT = (t == nT - 1);

        #pragma unroll
        for (int h2 = 0; h2 < 2; h2++) {
            float4 S[4], C[4];
            #pragma unroll
            for (int i = 0; i < 4; i++) {
                S[i] = make_float4(0.f, 0.f, 0.f, 0.f);
                C[i] = make_float4(0.f, 0.f, 0.f, 0.f);
            }
            // ---- S = Q K^T, C = Q' K'^T (3 split-MMAs each per k-step) ----
            #pragma unroll
            for (int nt4 = 0; nt4 < 4; nt4++) {
                const int nt = h2 * 4 + nt4;
                const int s  = nt * 8 + g;
                #pragma unroll
                for (int kk = 0; kk < 2; kk++) {
                    uint32_t bh0, bl0, bh1, bl1;
                    float2 x0 = *(const float2*)&tiles[cur].K[s][16 * kk + 2 * tg];
                    float2 x1 = *(const float2*)&tiles[cur].K[s][16 * kk + 2 * tg + 8];
                    split2(x0.x, x0.y, bh0, bl0);
                    split2(x1.x, x1.y, bh1, bl1);
                    mma16816(S[nt4], qAh[kk], bh0, bh1);
                    mma16816(S[nt4], qAl[kk], bh0, bh1);
                    mma16816(S[nt4], qAh[kk], bl0, bl1);
                    float2 y0 = *(const float2*)&tiles[cur].Kp[s][16 * kk + 2 * tg];
                    float2 y1 = *(const float2*)&tiles[cur].Kp[s][16 * kk + 2 * tg + 8];
                    split2(y0.x, y0.y, bh0, bl0);
                    split2(y1.x, y1.y, bh1, bl1);
                    mma16816(C[nt4], pAh_[kk], bh0, bh1);
                    mma16816(C[nt4], pAl_[kk], bh0, bh1);
                    mma16816(C[nt4], pAh_[kk], bl0, bl1);
                }
            }
            // ---- epilogue: P = exp(S * exp(-sqdist)); repack as A-frags ----
            uint32_t pAh[2][4], pAl[2][4];
            #pragma unroll
            for (int nt4 = 0; nt4 < 4; nt4++) {
                const int nt = h2 * 4 + nt4;
                const int cl = nt * 8 + 2 * tg;
                const float k20 = tiles[cur].k2[cl];
                const float k21 = tiles[cur].k2[cl + 1];
                float px = pfun(S[nt4].x, C[nt4].x, q2r0, k20);
                float py = pfun(S[nt4].y, C[nt4].y, q2r0, k21);
                float pz = pfun(S[nt4].z, C[nt4].z, q2r1, k20);
                float pw = pfun(S[nt4].w, C[nt4].w, q2r1, k21);
                if (maskT) {
                    const int cg = s0 + cl;
                    if (cg     > r0g) px = 0.f;
                    if (cg + 1 > r0g) py = 0.f;
                    if (cg     > r1g) pz = 0.f;
                    if (cg + 1 > r1g) pw = 0.f;
                }
                lsum0 += px + py;
                lsum1 += pz + pw;
                const int j2 = nt4 >> 1;
                const int rr = (nt4 & 1) * 2;
                split2(px, py, pAh[j2][rr],     pAl[j2][rr]);
                split2(pz, pw, pAh[j2][rr + 1], pAl[j2][rr + 1]);
            }
            // ---- O += P V (3 split-MMAs) ----
            #pragma unroll
            for (int j2 = 0; j2 < 2; j2++) {
                const int sl = 16 * (2 * h2 + j2) + 2 * tg;
                #pragma unroll
                for (int dt = 0; dt < 4; dt++) {
                    const int d = dt * 8 + g;
                    uint32_t vh0, vl0, vh1, vl1;
                    split2(tiles[cur].V[sl][d],     tiles[cur].V[sl + 1][d], vh0, vl0);
                    split2(tiles[cur].V[sl + 8][d], tiles[cur].V[sl + 9][d], vh1, vl1);
                    mma16816(O[dt], pAh[j2], vh0, vh1);
                    mma16816(O[dt], pAl[j2], vh0, vh1);
                    mma16816(O[dt], pAh[j2], vl0, vl1);
                }
            }
        }
    }

    // ---- finalize: reduce row sums, scale, store ----
    lsum0 += __shfl_xor_sync(0xffffffffu, lsum0, 1);
    lsum0 += __shfl_xor_sync(0xffffffffu, lsum0, 2);
    lsum1 += __shfl_xor_sync(0xffffffffu, lsum1, 1);
    lsum1 += __shfl_xor_sync(0xffffffffu, lsum1, 2);
    const float rl0 = 1.f / lsum0;
    const float rl1 = 1.f / lsum1;

    float* o0 = outg + ((size_t)(b * LLEN + r0g) * HH + h) * DD;
    float* o1 = outg + ((size_t)(b * LLEN + r1g) * HH + h) * DD;
    #pragma unroll
    for (int dt = 0; dt < 4; dt++) {
        const int col = dt * 8 + 2 * tg;
        *(float2*)(o0 + col) = make_float2(O[dt].x * rl0, O[dt].y * rl0);
        *(float2*)(o1 + col) = make_float2(O[dt].z * rl1, O[dt].w * rl1);
    }
}

extern "C" void kernel_launch(void* const* d_in, const int* in_sizes, int n_in,
                              void* d_out, int out_size)
{
    cudaFuncSetAttribute(gauss_attn_mma,
                         cudaFuncAttributeMaxDynamicSharedMemorySize, SMEM_BYTES);
    gauss_attn_mma<<<512, NTHR, SMEM_BYTES>>>(
        (const float*)d_in[0], (const float*)d_in[1], (const float*)d_in[2],
        (float*)d_out);
}

// round 5
// speedup vs baseline: 6.6323x; 1.7844x over previous
#include <cuda_runtime.h>
#include <cuda_bf16.h>
#include <cstdint>

#define LLEN 2048
#define HH   8
#define EE   32
#define DD   32
#define NTHR 128

// ---- pre-converted operand arrays (filled by pass-1 kernel) ----
__device__ __nv_bfloat16 g_Khi [16 * 2048 * 32];
__device__ __nv_bfloat16 g_Kphi[16 * 2048 * 32];
__device__ __nv_bfloat16 g_Vhi [16 * 2048 * 32];
__device__ __nv_bfloat16 g_Vlo [16 * 2048 * 32];
__device__ float         g_k2  [16 * 2048];

struct Tile {                       // 80-byte row stride -> conflict-free ldmatrix
    __nv_bfloat16 K [64][40];
    __nv_bfloat16 Kp[64][40];
    __nv_bfloat16 Vh[64][40];
    __nv_bfloat16 Vl[64][40];
    float k2[64];
};
#define SMEM_BYTES (2 * (int)sizeof(Tile))

__device__ __forceinline__ uint32_t smem_u32(const void* p) {
    uint32_t a;
    asm("{ .reg .u64 t; cvta.to.shared.u64 t, %1; cvt.u32.u64 %0, t; }"
        : "=r"(a) : "l"(p));
    return a;
}
__device__ __forceinline__ void cp16(uint32_t dst, const void* src) {
    asm volatile("cp.async.cg.shared.global [%0], [%1], 16;"
                 :: "r"(dst), "l"(src) : "memory");
}
#define CP_COMMIT() asm volatile("cp.async.commit_group;" ::: "memory")
#define CP_WAIT0()  asm volatile("cp.async.wait_group 0;" ::: "memory")

__device__ __forceinline__ void ldsm4(uint32_t* r, uint32_t a) {
    asm volatile("ldmatrix.sync.aligned.m8n8.x4.shared.b16 {%0,%1,%2,%3}, [%4];"
                 : "=r"(r[0]), "=r"(r[1]), "=r"(r[2]), "=r"(r[3]) : "r"(a));
}
__device__ __forceinline__ void ldsm4t(uint32_t* r, uint32_t a) {
    asm volatile("ldmatrix.sync.aligned.m8n8.x4.trans.shared.b16 {%0,%1,%2,%3}, [%4];"
                 : "=r"(r[0]), "=r"(r[1]), "=r"(r[2]), "=r"(r[3]) : "r"(a));
}
__device__ __forceinline__ void mma16816(float4& d, const uint32_t* a,
                                         uint32_t b0, uint32_t b1) {
    asm volatile(
        "mma.sync.aligned.m16n8k16.row.col.f32.bf16.bf16.f32 "
        "{%0,%1,%2,%3}, {%4,%5,%6,%7}, {%8,%9}, {%0,%1,%2,%3};"
        : "+f"(d.x), "+f"(d.y), "+f"(d.z), "+f"(d.w)
        : "r"(a[0]), "r"(a[1]), "r"(a[2]), "r"(a[3]), "r"(b0), "r"(b1));
}
__device__ __forceinline__ void split2(float x, float y, uint32_t& hi, uint32_t& lo) {
    __nv_bfloat162 h = __floats2bfloat162_rn(x, y);
    float2 hf = __bfloat1622float2(h);
    __nv_bfloat162 l = __floats2bfloat162_rn(x - hf.x, y - hf.y);
    hi = *reinterpret_cast<uint32_t*>(&h);
    lo = *reinterpret_cast<uint32_t*>(&l);
}
__device__ __forceinline__ uint32_t pack2(float x, float y) {
    __nv_bfloat162 h = __floats2bfloat162_rn(x, y);
    return *reinterpret_cast<uint32_t*>(&h);
}
__device__ __forceinline__ float pfun(float s, float c, float q2, float k2) {
    float sq = fmaxf(q2 + k2 - 2.f * c, 0.f);
    return __expf(s * __expf(-sq));
}

// ================= pass 1: convert K, K', V; compute k2 =================
__global__ void __launch_bounds__(256)
preconvert(const float* __restrict__ kg, const float* __restrict__ vg)
{
    const int idx = blockIdx.x * 256 + threadIdx.x;   // 32768 rows
    const int r  = idx & 2047;
    const int bh = idx >> 11;
    const int b = bh >> 3, h = bh & 7;
    const float inv2 = 0.03125f;

    const float4* ks = (const float4*)(kg + ((size_t)(b * LLEN + r) * HH + h) * EE);
    __nv_bfloat162* kd = (__nv_bfloat162*)(g_Khi + ((size_t)bh * LLEN + r) * EE);
    #pragma unroll
    for (int i = 0; i < 8; i++) {
        float4 t = ks[i];
        kd[2*i]   = __floats2bfloat162_rn(t.x, t.y);
        kd[2*i+1] = __floats2bfloat162_rn(t.z, t.w);
    }
    const int rk = h * 256 + (r >> 3), hk = r & 7;     // scrambled reshape row
    const float4* kps = (const float4*)(kg + ((size_t)(b * LLEN + rk) * HH + hk) * EE);
    __nv_bfloat162* kpd = (__nv_bfloat162*)(g_Kphi + ((size_t)bh * LLEN + r) * EE);
    float k2 = 0.f;
    #pragma unroll
    for (int i = 0; i < 8; i++) {
        float4 t = kps[i];
        k2 += t.x*t.x + t.y*t.y + t.z*t.z + t.w*t.w;
        kpd[2*i]   = __floats2bfloat162_rn(t.x, t.y);
        kpd[2*i+1] = __floats2bfloat162_rn(t.z, t.w);
    }
    g_k2[(size_t)bh * LLEN + r] = k2 * inv2;

    const float4* vs = (const float4*)(vg + ((size_t)(b * LLEN + r) * HH + h) * DD);
    __nv_bfloat162* vh = (__nv_bfloat162*)(g_Vhi + ((size_t)bh * LLEN + r) * DD);
    __nv_bfloat162* vl = (__nv_bfloat162*)(g_Vlo + ((size_t)bh * LLEN + r) * DD);
    #pragma unroll
    for (int i = 0; i < 8; i++) {
        float4 t = vs[i];
        __nv_bfloat162 h0 = __floats2bfloat162_rn(t.x, t.y);
        __nv_bfloat162 h1 = __floats2bfloat162_rn(t.z, t.w);
        float2 f0 = __bfloat1622float2(h0), f1 = __bfloat1622float2(h1);
        vh[2*i]   = h0;
        vh[2*i+1] = h1;
        vl[2*i]   = __floats2bfloat162_rn(t.x - f0.x, t.y - f0.y);
        vl[2*i+1] = __floats2bfloat162_rn(t.z - f1.x, t.w - f1.y);
    }
}

// ================= main kernel =================
__device__ __forceinline__ void issue_tile(Tile* tb, int bh, int s0, int tid) {
    const int r = tid >> 1, half = tid & 1;
    const size_t row = (size_t)bh * LLEN + s0 + r;
    const __nv_bfloat16* k  = g_Khi  + row * EE;
    const __nv_bfloat16* kp = g_Kphi + row * EE;
    const __nv_bfloat16* vh = g_Vhi  + row * DD;
    const __nv_bfloat16* vl = g_Vlo  + row * DD;
    #pragma unroll
    for (int j = 0; j < 2; j++) {
        const int c = half * 2 + j;            // 16B chunk (8 bf16)
        cp16(smem_u32(&tb->K [r][c * 8]), k  + c * 8);
        cp16(smem_u32(&tb->Kp[r][c * 8]), kp + c * 8);
        cp16(smem_u32(&tb->Vh[r][c * 8]), vh + c * 8);
        cp16(smem_u32(&tb->Vl[r][c * 8]), vl + c * 8);
    }
    if (tid < 16) cp16(smem_u32(&tb->k2[tid * 4]), g_k2 + (size_t)bh * LLEN + s0 + tid * 4);
}

__global__ void __launch_bounds__(NTHR, 4)
gauss_attn_mma2(const float* __restrict__ qg, float* __restrict__ outg)
{
    extern __shared__ Tile tiles[];   // [2]
    const int tid  = threadIdx.x;
    const int wid  = tid >> 5;
    const int lane = tid & 31;
    const int g    = lane >> 2;
    const int tg   = lane & 3;
    const int i8   = lane & 7;
    const int g4lo = (lane >> 3) & 1;
    const int g4hi = lane >> 4;

    const int bx = blockIdx.x;
    const int lt = 31 - (bx >> 4);        // heavy diagonal tiles first
    const int bh = bx & 15;
    const int b  = bh >> 3, h = bh & 7;
    const int l0 = lt * 64;
    const int nT = lt + 1;

    const float inv2 = 0.03125f;                   // 1/32
    const float inv3 = 0.005524271728019903f;      // 32^-1.5

    const int r0g = l0 + wid * 16 + g;
    const int r1g = r0g + 8;

    issue_tile(&tiles[0], bh, 0, tid);
    CP_COMMIT();

    // ---- Q / Q' A-fragments (single bf16) + q2 ----
    uint32_t qA[2][4], pA_[2][4];
    float q2r0 = 0.f, q2r1 = 0.f;
    #pragma unroll
    for (int kk = 0; kk < 2; kk++) {
        const float* p0 = qg + ((size_t)(b * LLEN + r0g) * HH + h) * EE + 16 * kk + 2 * tg;
        const float* p1 = qg + ((size_t)(b * LLEN + r1g) * HH + h) * EE + 16 * kk + 2 * tg;
        float2 a0 = *(const float2*)p0;
        float2 a1 = *(const float2*)p1;
        float2 a2 = *(const float2*)(p0 + 8);
        float2 a3 = *(const float2*)(p1 + 8);
        qA[kk][0] = pack2(a0.x * inv3, a0.y * inv3);
        qA[kk][1] = pack2(a1.x * inv3, a1.y * inv3);
        qA[kk][2] = pack2(a2.x * inv3, a2.y * inv3);
        qA[kk][3] = pack2(a3.x * inv3, a3.y * inv3);

        const int lq0 = h * 256 + (r0g >> 3), hq0 = r0g & 7;
        const int lq1 = h * 256 + (r1g >> 3), hq1 = r1g & 7;
        const float* s0p = qg + ((size_t)(b * LLEN + lq0) * HH + hq0) * EE + 16 * kk + 2 * tg;
        const float* s1p = qg + ((size_t)(b * LLEN + lq1) * HH + hq1) * EE + 16 * kk + 2 * tg;
        float2 b0 = *(const float2*)s0p;
        float2 b1 = *(const float2*)s1p;
        float2 b2 = *(const float2*)(s0p + 8);
        float2 b3 = *(const float2*)(s1p + 8);
        q2r0 += b0.x*b0.x + b0.y*b0.y + b2.x*b2.x + b2.y*b2.y;
        q2r1 += b1.x*b1.x + b1.y*b1.y + b3.x*b3.x + b3.y*b3.y;
        pA_[kk][0] = pack2(b0.x * inv2, b0.y * inv2);
        pA_[kk][1] = pack2(b1.x * inv2, b1.y * inv2);
        pA_[kk][2] = pack2(b2.x * inv2, b2.y * inv2);
        pA_[kk][3] = pack2(b3.x * inv2, b3.y * inv2);
    }
    q2r0 += __shfl_xor_sync(0xffffffffu, q2r0, 1);
    q2r0 += __shfl_xor_sync(0xffffffffu, q2r0, 2);
    q2r1 += __shfl_xor_sync(0xffffffffu, q2r1, 1);
    q2r1 += __shfl_xor_sync(0xffffffffu, q2r1, 2);
    q2r0 *= inv2;  q2r1 *= inv2;

    float4 O[4];
    #pragma unroll
    for (int i = 0; i < 4; i++) O[i] = make_float4(0.f, 0.f, 0.f, 0.f);
    float lsum0 = 0.f, lsum1 = 0.f;

    for (int t = 0; t < nT; t++) {
        const int cur = t & 1;
        CP_WAIT0();
        __syncthreads();
        if (t + 1 < nT) {
            issue_tile(&tiles[cur ^ 1], bh, (t + 1) * 64, tid);
            CP_COMMIT();
        }
        Tile& tb = tiles[cur];
        const uint32_t kb  = smem_u32(&tb.K [0][0]);
        const uint32_t kpb = smem_u32(&tb.Kp[0][0]);
        const uint32_t vhb = smem_u32(&tb.Vh[0][0]);
        const uint32_t vlb = smem_u32(&tb.Vl[0][0]);

        const int  s0    = t * 64;
        const bool maskT = (t == nT - 1);

        #pragma unroll
        for (int h2 = 0; h2 < 2; h2++) {
            float4 S[4], C[4];
            #pragma unroll
            for (int i = 0; i < 4; i++) {
                S[i] = make_float4(0.f, 0.f, 0.f, 0.f);
                C[i] = make_float4(0.f, 0.f, 0.f, 0.f);
            }
            // ---- S = Q K^T, C = Q' K'^T  (single bf16 MMA per k16) ----
            #pragma unroll
            for (int p = 0; p < 2; p++) {
                const uint32_t rowoff = (uint32_t)(((h2 * 4 + p * 2 + g4hi) * 8 + i8) * 80);
                #pragma unroll
                for (int kk = 0; kk < 2; kk++) {
                    const uint32_t off = rowoff + kk * 32 + g4lo * 16;
                    uint32_t rB[4];
                    ldsm4(rB, kb + off);
                    mma16816(S[p*2],   qA[kk], rB[0], rB[1]);
                    mma16816(S[p*2+1], qA[kk], rB[2], rB[3]);
                    ldsm4(rB, kpb + off);
                    mma16816(C[p*2],   pA_[kk], rB[0], rB[1]);
                    mma16816(C[p*2+1], pA_[kk], rB[2], rB[3]);
                }
            }
            // ---- epilogue: P = exp(S * exp(-sqdist)); repack as PV A-frags ----
            uint32_t pAh[2][4], pAl[2][4];
            #pragma unroll
            for (int nt4 = 0; nt4 < 4; nt4++) {
                const int nt = h2 * 4 + nt4;
                const int cl = nt * 8 + 2 * tg;
                const float2 k2p = *(const float2*)&tb.k2[cl];
                float px = pfun(S[nt4].x, C[nt4].x, q2r0, k2p.x);
                float py = pfun(S[nt4].y, C[nt4].y, q2r0, k2p.y);
                float pz = pfun(S[nt4].z, C[nt4].z, q2r1, k2p.x);
                float pw = pfun(S[nt4].w, C[nt4].w, q2r1, k2p.y);
                if (maskT) {
                    const int cg = s0 + cl;
                    if (cg     > r0g) px = 0.f;
                    if (cg + 1 > r0g) py = 0.f;
                    if (cg     > r1g) pz = 0.f;
                    if (cg + 1 > r1g) pw = 0.f;
                }
                lsum0 += px + py;
                lsum1 += pz + pw;
                const int j2 = nt4 >> 1;
                const int rr = (nt4 & 1) * 2;
                split2(px, py, pAh[j2][rr],     pAl[j2][rr]);
                split2(pz, pw, pAh[j2][rr + 1], pAl[j2][rr + 1]);
            }
            // ---- O += P V  (3-term split) ----
            #pragma unroll
            for (int j2 = 0; j2 < 2; j2++) {
                const uint32_t srow = (uint32_t)((h2 * 32 + j2 * 16 + g4lo * 8 + i8) * 80);
                #pragma unroll
                for (int dp = 0; dp < 2; dp++) {
                    const uint32_t off = srow + (dp * 16 + g4hi * 8) * 2;
                    uint32_t vh[4], vl[4];
                    ldsm4t(vh, vhb + off);
                    ldsm4t(vl, vlb + off);
                    mma16816(O[dp*2],   pAh[j2], vh[0], vh[1]);
                    mma16816(O[dp*2],   pAl[j2], vh[0], vh[1]);
                    mma16816(O[dp*2],   pAh[j2], vl[0], vl[1]);
                    mma16816(O[dp*2+1], pAh[j2], vh[2], vh[3]);
                    mma16816(O[dp*2+1], pAl[j2], vh[2], vh[3]);
                    mma16816(O[dp*2+1], pAh[j2], vl[2], vl[3]);
                }
            }
        }
    }

    // ---- finalize ----
    lsum0 += __shfl_xor_sync(0xffffffffu, lsum0, 1);
    lsum0 += __shfl_xor_sync(0xffffffffu, lsum0, 2);
    lsum1 += __shfl_xor_sync(0xffffffffu, lsum1, 1);
    lsum1 += __shfl_xor_sync(0xffffffffu, lsum1, 2);
    const float rl0 = 1.f / lsum0;
    const float rl1 = 1.f / lsum1;

    float* o0 = outg + ((size_t)(b * LLEN + r0g) * HH + h) * DD;
    float* o1 = outg + ((size_t)(b * LLEN + r1g) * HH + h) * DD;
    #pragma unroll
    for (int dt = 0; dt < 4; dt++) {
        const int col = dt * 8 + 2 * tg;
        *(float2*)(o0 + col) = make_float2(O[dt].x * rl0, O[dt].y * rl0);
        *(float2*)(o1 + col) = make_float2(O[dt].z * rl1, O[dt].w * rl1);
    }
}

extern "C" void kernel_launch(void* const* d_in, const int* in_sizes, int n_in,
                              void* d_out, int out_size)
{
    const float* q = (const float*)d_in[0];
    const float* k = (const float*)d_in[1];
    const float* v = (const float*)d_in[2];

    preconvert<<<128, 256>>>(k, v);

    cudaFuncSetAttribute(gauss_attn_mma2,
                         cudaFuncAttributeMaxDynamicSharedMemorySize, SMEM_BYTES);
    gauss_attn_mma2<<<512, NTHR, SMEM_BYTES>>>(q, (float*)d_out);
}

// round 6
// speedup vs baseline: 7.0928x; 1.0694x over previous
#include <cuda_runtime.h>
#include <cuda_bf16.h>
#include <cstdint>

#define LLEN 2048
#define HH   8
#define EE   32
#define DD   32
#define NTHR 128
#define L2E  1.4426950408889634f

// ---- pre-converted operand arrays (filled by pass-1 kernel) ----
__device__ __nv_bfloat16 g_Khi [16 * 2048 * 32];
__device__ __nv_bfloat16 g_Kphi[16 * 2048 * 32];
__device__ __nv_bfloat16 g_Vhi [16 * 2048 * 32];
__device__ __nv_bfloat16 g_Vlo [16 * 2048 * 32];
__device__ float         g_beta[16 * 2048];      // exp(-||k'||^2 / 32)

struct Tile {                       // 80-byte row stride -> conflict-free ldmatrix
    __nv_bfloat16 K [64][40];
    __nv_bfloat16 Kp[64][40];
    __nv_bfloat16 Vh[64][40];
    __nv_bfloat16 Vl[64][40];
    float beta[64];
};
#define SMEM_BYTES (2 * (int)sizeof(Tile))

__device__ __forceinline__ uint32_t smem_u32(const void* p) {
    uint32_t a;
    asm("{ .reg .u64 t; cvta.to.shared.u64 t, %1; cvt.u32.u64 %0, t; }"
        : "=r"(a) : "l"(p));
    return a;
}
__device__ __forceinline__ void cp16(uint32_t dst, const void* src) {
    asm volatile("cp.async.cg.shared.global [%0], [%1], 16;"
                 :: "r"(dst), "l"(src) : "memory");
}
#define CP_COMMIT() asm volatile("cp.async.commit_group;" ::: "memory")
#define CP_WAIT0()  asm volatile("cp.async.wait_group 0;" ::: "memory")

__device__ __forceinline__ void ldsm4(uint32_t* r, uint32_t a) {
    asm volatile("ldmatrix.sync.aligned.m8n8.x4.shared.b16 {%0,%1,%2,%3}, [%4];"
                 : "=r"(r[0]), "=r"(r[1]), "=r"(r[2]), "=r"(r[3]) : "r"(a));
}
__device__ __forceinline__ void ldsm4t(uint32_t* r, uint32_t a) {
    asm volatile("ldmatrix.sync.aligned.m8n8.x4.trans.shared.b16 {%0,%1,%2,%3}, [%4];"
                 : "=r"(r[0]), "=r"(r[1]), "=r"(r[2]), "=r"(r[3]) : "r"(a));
}
__device__ __forceinline__ void mma16816(float4& d, const uint32_t* a,
                                         uint32_t b0, uint32_t b1) {
    asm volatile(
        "mma.sync.aligned.m16n8k16.row.col.f32.bf16.bf16.f32 "
        "{%0,%1,%2,%3}, {%4,%5,%6,%7}, {%8,%9}, {%0,%1,%2,%3};"
        : "+f"(d.x), "+f"(d.y), "+f"(d.z), "+f"(d.w)
        : "r"(a[0]), "r"(a[1]), "r"(a[2]), "r"(a[3]), "r"(b0), "r"(b1));
}
__device__ __forceinline__ void split2(float x, float y, uint32_t& hi, uint32_t& lo) {
    __nv_bfloat162 h = __floats2bfloat162_rn(x, y);
    float2 hf = __bfloat1622float2(h);
    __nv_bfloat162 l = __floats2bfloat162_rn(x - hf.x, y - hf.y);
    hi = *reinterpret_cast<uint32_t*>(&h);
    lo = *reinterpret_cast<uint32_t*>(&l);
}
__device__ __forceinline__ uint32_t pack2(float x, float y) {
    __nv_bfloat162 h = __floats2bfloat162_rn(x, y);
    return *reinterpret_cast<uint32_t*>(&h);
}
__device__ __forceinline__ float ex2(float x) {
    float r;
    asm("ex2.approx.f32 %0, %1;" : "=f"(r) : "f"(x));
    return r;
}

// ================= pass 1: convert K, K', V; compute beta =================
__global__ void __launch_bounds__(256)
preconvert(const float* __restrict__ kg, const float* __restrict__ vg)
{
    const int idx = blockIdx.x * 256 + threadIdx.x;   // 32768 rows
    const int r  = idx & 2047;
    const int bh = idx >> 11;
    const int b = bh >> 3, h = bh & 7;
    const float inv2 = 0.03125f;

    const float4* ks = (const float4*)(kg + ((size_t)(b * LLEN + r) * HH + h) * EE);
    __nv_bfloat162* kd = (__nv_bfloat162*)(g_Khi + ((size_t)bh * LLEN + r) * EE);
    #pragma unroll
    for (int i = 0; i < 8; i++) {
        float4 t = ks[i];
        kd[2*i]   = __floats2bfloat162_rn(t.x, t.y);
        kd[2*i+1] = __floats2bfloat162_rn(t.z, t.w);
    }
    const int rk = h * 256 + (r >> 3), hk = r & 7;     // scrambled reshape row
    const float4* kps = (const float4*)(kg + ((size_t)(b * LLEN + rk) * HH + hk) * EE);
    __nv_bfloat162* kpd = (__nv_bfloat162*)(g_Kphi + ((size_t)bh * LLEN + r) * EE);
    float k2 = 0.f;
    #pragma unroll
    for (int i = 0; i < 8; i++) {
        float4 t = kps[i];
        k2 += t.x*t.x + t.y*t.y + t.z*t.z + t.w*t.w;
        kpd[2*i]   = __floats2bfloat162_rn(t.x, t.y);
        kpd[2*i+1] = __floats2bfloat162_rn(t.z, t.w);
    }
    g_beta[(size_t)bh * LLEN + r] = __expf(-k2 * inv2);

    const float4* vs = (const float4*)(vg + ((size_t)(b * LLEN + r) * HH + h) * DD);
    __nv_bfloat162* vh = (__nv_bfloat162*)(g_Vhi + ((size_t)bh * LLEN + r) * DD);
    __nv_bfloat162* vl = (__nv_bfloat162*)(g_Vlo + ((size_t)bh * LLEN + r) * DD);
    #pragma unroll
    for (int i = 0; i < 8; i++) {
        float4 t = vs[i];
        __nv_bfloat162 h0 = __floats2bfloat162_rn(t.x, t.y);
        __nv_bfloat162 h1 = __floats2bfloat162_rn(t.z, t.w);
        float2 f0 = __bfloat1622float2(h0), f1 = __bfloat1622float2(h1);
        vh[2*i]   = h0;
        vh[2*i+1] = h1;
        vl[2*i]   = __floats2bfloat162_rn(t.x - f0.x, t.y - f0.y);
        vl[2*i+1] = __floats2bfloat162_rn(t.z - f1.x, t.w - f1.y);
    }
}

// ================= main kernel =================
__global__ void __launch_bounds__(NTHR, 4)
gauss_attn_mma3(const float* __restrict__ qg, float* __restrict__ outg)
{
    extern __shared__ Tile tiles[];   // [2]
    const int tid  = threadIdx.x;
    const int wid  = tid >> 5;
    const int lane = tid & 31;
    const int g    = lane >> 2;
    const int tg   = lane & 3;
    const int i8   = lane & 7;
    const int g4lo = (lane >> 3) & 1;
    const int g4hi = lane >> 4;

    const int bx = blockIdx.x;
    const int lt = 31 - (bx >> 4);        // heavy diagonal tiles first
    const int bh = bx & 15;
    const int b  = bh >> 3, h = bh & 7;
    const int l0 = lt * 64;
    const int nT = lt + 1;

    const float inv2 = 0.03125f;                   // 1/32
    const float inv3 = 0.005524271728019903f;      // 32^-1.5

    const int r0g = l0 + wid * 16 + g;
    const int r1g = r0g + 8;
    const int rmaxW = l0 + wid * 16 + 15;

    // ---- incremental gmem pointers for tile loads ----
    const int lr = tid >> 1, half = tid & 1;
    const size_t rowbase = ((size_t)bh * LLEN + lr) * EE + half * 16;
    const __nv_bfloat16* kP  = g_Khi  + rowbase;
    const __nv_bfloat16* kpP = g_Kphi + rowbase;
    const __nv_bfloat16* vhP = g_Vhi  + rowbase;
    const __nv_bfloat16* vlP = g_Vlo  + rowbase;
    const float*         bP  = g_beta + (size_t)bh * LLEN + tid * 4;

    // issue tile 0 into buffer 0
    {
        Tile* tn = &tiles[0];
        cp16(smem_u32(&tn->K [lr][half*16]),   kP);
        cp16(smem_u32(&tn->K [lr][half*16+8]), kP  + 8);
        cp16(smem_u32(&tn->Kp[lr][half*16]),   kpP);
        cp16(smem_u32(&tn->Kp[lr][half*16+8]), kpP + 8);
        cp16(smem_u32(&tn->Vh[lr][half*16]),   vhP);
        cp16(smem_u32(&tn->Vh[lr][half*16+8]), vhP + 8);
        cp16(smem_u32(&tn->Vl[lr][half*16]),   vlP);
        cp16(smem_u32(&tn->Vl[lr][half*16+8]), vlP + 8);
        if (tid < 16) cp16(smem_u32(&tn->beta[tid*4]), bP);
    }
    CP_COMMIT();
    kP += 2048; kpP += 2048; vhP += 2048; vlP += 2048; bP += 64;

    // ---- Q / Q' fragments: load raw, compute q2 and alpha, then pack ----
    float2 qa[2][4], qp[2][4];
    float q2r0 = 0.f, q2r1 = 0.f;
    #pragma unroll
    for (int kk = 0; kk < 2; kk++) {
        const float* p0 = qg + ((size_t)(b * LLEN + r0g) * HH + h) * EE + 16 * kk + 2 * tg;
        const float* p1 = qg + ((size_t)(b * LLEN + r1g) * HH + h) * EE + 16 * kk + 2 * tg;
        qa[kk][0] = *(const float2*)p0;
        qa[kk][1] = *(const float2*)p1;
        qa[kk][2] = *(const float2*)(p0 + 8);
        qa[kk][3] = *(const float2*)(p1 + 8);

        const int lq0 = h * 256 + (r0g >> 3), hq0 = r0g & 7;
        const int lq1 = h * 256 + (r1g >> 3), hq1 = r1g & 7;
        const float* s0p = qg + ((size_t)(b * LLEN + lq0) * HH + hq0) * EE + 16 * kk + 2 * tg;
        const float* s1p = qg + ((size_t)(b * LLEN + lq1) * HH + hq1) * EE + 16 * kk + 2 * tg;
        qp[kk][0] = *(const float2*)s0p;
        qp[kk][1] = *(const float2*)s1p;
        qp[kk][2] = *(const float2*)(s0p + 8);
        qp[kk][3] = *(const float2*)(s1p + 8);
        q2r0 += qp[kk][0].x*qp[kk][0].x + qp[kk][0].y*qp[kk][0].y
              + qp[kk][2].x*qp[kk][2].x + qp[kk][2].y*qp[kk][2].y;
        q2r1 += qp[kk][1].x*qp[kk][1].x + qp[kk][1].y*qp[kk][1].y
              + qp[kk][3].x*qp[kk][3].x + qp[kk][3].y*qp[kk][3].y;
    }
    q2r0 += __shfl_xor_sync(0xffffffffu, q2r0, 1);
    q2r0 += __shfl_xor_sync(0xffffffffu, q2r0, 2);
    q2r1 += __shfl_xor_sync(0xffffffffu, q2r1, 1);
    q2r1 += __shfl_xor_sync(0xffffffffu, q2r1, 2);
    const float al0 = __expf(-q2r0 * inv2);        // alpha = exp(-||q'||^2/32)
    const float al1 = __expf(-q2r1 * inv2);

    const float sc0 = inv3 * L2E * al0;            // fold scale, log2e, alpha
    const float sc1 = inv3 * L2E * al1;
    const float cs  = inv2 * 2.f * L2E;            // Q' scale: 2*log2e folded

    uint32_t qA[2][4], pA_[2][4];
    #pragma unroll
    for (int kk = 0; kk < 2; kk++) {
        qA[kk][0] = pack2(qa[kk][0].x * sc0, qa[kk][0].y * sc0);
        qA[kk][1] = pack2(qa[kk][1].x * sc1, qa[kk][1].y * sc1);
        qA[kk][2] = pack2(qa[kk][2].x * sc0, qa[kk][2].y * sc0);
        qA[kk][3] = pack2(qa[kk][3].x * sc1, qa[kk][3].y * sc1);
        pA_[kk][0] = pack2(qp[kk][0].x * cs, qp[kk][0].y * cs);
        pA_[kk][1] = pack2(qp[kk][1].x * cs, qp[kk][1].y * cs);
        pA_[kk][2] = pack2(qp[kk][2].x * cs, qp[kk][2].y * cs);
        pA_[kk][3] = pack2(qp[kk][3].x * cs, qp[kk][3].y * cs);
    }

    float4 O[4];
    #pragma unroll
    for (int i = 0; i < 4; i++) O[i] = make_float4(0.f, 0.f, 0.f, 0.f);
    float lsum0 = 0.f, lsum1 = 0.f;

    for (int t = 0; t < nT; t++) {
        const int cur = t & 1;
        CP_WAIT0();
        __syncthreads();
        if (t + 1 < nT) {
            Tile* tn = &tiles[cur ^ 1];
            cp16(smem_u32(&tn->K [lr][half*16]),   kP);
            cp16(smem_u32(&tn->K [lr][half*16+8]), kP  + 8);
            cp16(smem_u32(&tn->Kp[lr][half*16]),   kpP);
            cp16(smem_u32(&tn->Kp[lr][half*16+8]), kpP + 8);
            cp16(smem_u32(&tn->Vh[lr][half*16]),   vhP);
            cp16(smem_u32(&tn->Vh[lr][half*16+8]), vhP + 8);
            cp16(smem_u32(&tn->Vl[lr][half*16]),   vlP);
            cp16(smem_u32(&tn->Vl[lr][half*16+8]), vlP + 8);
            if (tid < 16) cp16(smem_u32(&tn->beta[tid*4]), bP);
            CP_COMMIT();
            kP += 2048; kpP += 2048; vhP += 2048; vlP += 2048; bP += 64;
        }
        Tile& tb = tiles[cur];
        const uint32_t kb  = smem_u32(&tb.K [0][0]);
        const uint32_t kpb = smem_u32(&tb.Kp[0][0]);
        const uint32_t vhb = smem_u32(&tb.Vh[0][0]);
        const uint32_t vlb = smem_u32(&tb.Vl[0][0]);

        const int  s0    = t * 64;
        const bool maskT = (t == nT - 1);

        #pragma unroll
        for (int h2 = 0; h2 < 2; h2++) {
            if (s0 + h2 * 32 > rmaxW) continue;   // fully-masked half (warp-uniform)
            float4 S[4], C[4];
            #pragma unroll
            for (int i = 0; i < 4; i++) {
                S[i] = make_float4(0.f, 0.f, 0.f, 0.f);
                C[i] = make_float4(0.f, 0.f, 0.f, 0.f);
            }
            // ---- S' = L2E*alpha*scale*(Q K^T),  C' = 2*L2E/32*(Q' K'^T) ----
            #pragma unroll
            for (int p = 0; p < 2; p++) {
                const uint32_t rowoff = (uint32_t)(((h2 * 4 + p * 2 + g4hi) * 8 + i8) * 80);
                #pragma unroll
                for (int kk = 0; kk < 2; kk++) {
                    const uint32_t off = rowoff + kk * 32 + g4lo * 16;
                    uint32_t rB[4];
                    ldsm4(rB, kb + off);
                    mma16816(S[p*2],   qA[kk], rB[0], rB[1]);
                    mma16816(S[p*2+1], qA[kk], rB[2], rB[3]);
                    ldsm4(rB, kpb + off);
                    mma16816(C[p*2],   pA_[kk], rB[0], rB[1]);
                    mma16816(C[p*2+1], pA_[kk], rB[2], rB[3]);
                }
            }
            // ---- epilogue: p = 2^( S' * 2^(C') * beta ) ----
            uint32_t pAh[2][4], pAl[2][4];
            #pragma unroll
            for (int nt4 = 0; nt4 < 4; nt4++) {
                const int nt = h2 * 4 + nt4;
                const int cl = nt * 8 + 2 * tg;
                const float2 bb = *(const float2*)&tb.beta[cl];
                float px = ex2(S[nt4].x * ex2(C[nt4].x) * bb.x);
                float py = ex2(S[nt4].y * ex2(C[nt4].y) * bb.y);
                float pz = ex2(S[nt4].z * ex2(C[nt4].z) * bb.x);
                float pw = ex2(S[nt4].w * ex2(C[nt4].w) * bb.y);
                if (maskT) {
                    const int cg = s0 + cl;
                    if (cg     > r0g) px = 0.f;
                    if (cg + 1 > r0g) py = 0.f;
                    if (cg     > r1g) pz = 0.f;
                    if (cg + 1 > r1g) pw = 0.f;
                }
                lsum0 += px + py;
                lsum1 += pz + pw;
                const int j2 = nt4 >> 1;
                const int rr = (nt4 & 1) * 2;
                split2(px, py, pAh[j2][rr],     pAl[j2][rr]);
                split2(pz, pw, pAh[j2][rr + 1], pAl[j2][rr + 1]);
            }
            // ---- O += P V  (3-term split) ----
            #pragma unroll
            for (int j2 = 0; j2 < 2; j2++) {
                const uint32_t srow = (uint32_t)((h2 * 32 + j2 * 16 + g4lo * 8 + i8) * 80);
                #pragma unroll
                for (int dp = 0; dp < 2; dp++) {
                    const uint32_t off = srow + (dp * 16 + g4hi * 8) * 2;
                    uint32_t vh[4], vl[4];
                    ldsm4t(vh, vhb + off);
                    ldsm4t(vl, vlb + off);
                    mma16816(O[dp*2],   pAh[j2], vh[0], vh[1]);
                    mma16816(O[dp*2],   pAl[j2], vh[0], vh[1]);
                    mma16816(O[dp*2],   pAh[j2], vl[0], vl[1]);
                    mma16816(O[dp*2+1], pAh[j2], vh[2], vh[3]);
                    mma16816(O[dp*2+1], pAl[j2], vh[2], vh[3]);
                    mma16816(O[dp*2+1], pAh[j2], vl[2], vl[3]);
                }
            }
        }
    }

    // ---- finalize ----
    lsum0 += __shfl_xor_sync(0xffffffffu, lsum0, 1);
    lsum0 += __shfl_xor_sync(0xffffffffu, lsum0, 2);
    lsum1 += __shfl_xor_sync(0xffffffffu, lsum1, 1);
    lsum1 += __shfl_xor_sync(0xffffffffu, lsum1, 2);
    const float rl0 = 1.f / lsum0;
    const float rl1 = 1.f / lsum1;

    float* o0 = outg + ((size_t)(b * LLEN + r0g) * HH + h) * DD;
    float* o1 = outg + ((size_t)(b * LLEN + r1g) * HH + h) * DD;
    #pragma unroll
    for (int dt = 0; dt < 4; dt++) {
        const int col = dt * 8 + 2 * tg;
        *(float2*)(o0 + col) = make_float2(O[dt].x * rl0, O[dt].y * rl0);
        *(float2*)(o1 + col) = make_float2(O[dt].z * rl1, O[dt].w * rl1);
    }
}

extern "C" void kernel_launch(void* const* d_in, const int* in_sizes, int n_in,
                              void* d_out, int out_size)
{
    const float* q = (const float*)d_in[0];
    const float* k = (const float*)d_in[1];
    const float* v = (const float*)d_in[2];

    preconvert<<<128, 256>>>(k, v);

    cudaFuncSetAttribute(gauss_attn_mma3,
                         cudaFuncAttributeMaxDynamicSharedMemorySize, SMEM_BYTES);
    gauss_attn_mma3<<<512, NTHR, SMEM_BYTES>>>(q, (float*)d_out);
}

// round 7
// speedup vs baseline: 8.4931x; 1.1974x over previous
#include <cuda_runtime.h>
#include <cuda_fp16.h>
#include <cstdint>

#define LLEN 2048
#define HH   8
#define EE   32
#define DD   32
#define NTHR 128
#define L2E  1.4426950408889634f

// ---- pre-converted fp16 operand arrays (filled by pass-1 kernel) ----
__device__ __half g_Kh [16 * 2048 * 32];
__device__ __half g_Kph[16 * 2048 * 32];
__device__ __half g_Vh [16 * 2048 * 32];
__device__ float  g_beta[16 * 2048];          // exp(-||k'||^2 / 32)

struct Tile {                  // 80-byte row stride -> conflict-free ldmatrix
    __half K [64][40];
    __half Kp[64][40];
    __half Vh[64][40];
    float beta[64];
};
#define SMEM_BYTES (2 * (int)sizeof(Tile))

__device__ __forceinline__ uint32_t smem_u32(const void* p) {
    uint32_t a;
    asm("{ .reg .u64 t; cvta.to.shared.u64 t, %1; cvt.u32.u64 %0, t; }"
        : "=r"(a) : "l"(p));
    return a;
}
__device__ __forceinline__ void cp16(uint32_t dst, const void* src) {
    asm volatile("cp.async.cg.shared.global [%0], [%1], 16;"
                 :: "r"(dst), "l"(src) : "memory");
}
#define CP_COMMIT() asm volatile("cp.async.commit_group;" ::: "memory")
#define CP_WAIT0()  asm volatile("cp.async.wait_group 0;" ::: "memory")

__device__ __forceinline__ void ldsm4(uint32_t* r, uint32_t a) {
    asm volatile("ldmatrix.sync.aligned.m8n8.x4.shared.b16 {%0,%1,%2,%3}, [%4];"
                 : "=r"(r[0]), "=r"(r[1]), "=r"(r[2]), "=r"(r[3]) : "r"(a));
}
__device__ __forceinline__ void ldsm4t(uint32_t* r, uint32_t a) {
    asm volatile("ldmatrix.sync.aligned.m8n8.x4.trans.shared.b16 {%0,%1,%2,%3}, [%4];"
                 : "=r"(r[0]), "=r"(r[1]), "=r"(r[2]), "=r"(r[3]) : "r"(a));
}
__device__ __forceinline__ void mma16816(float4& d, const uint32_t* a,
                                         uint32_t b0, uint32_t b1) {
    asm volatile(
        "mma.sync.aligned.m16n8k16.row.col.f32.f16.f16.f32 "
        "{%0,%1,%2,%3}, {%4,%5,%6,%7}, {%8,%9}, {%0,%1,%2,%3};"
        : "+f"(d.x), "+f"(d.y), "+f"(d.z), "+f"(d.w)
        : "r"(a[0]), "r"(a[1]), "r"(a[2]), "r"(a[3]), "r"(b0), "r"(b1));
}
__device__ __forceinline__ uint32_t pack2h(float x, float y) {
    __half2 h = __floats2half2_rn(x, y);
    return *reinterpret_cast<uint32_t*>(&h);
}
__device__ __forceinline__ float ex2(float x) {
    float r;
    asm("ex2.approx.f32 %0, %1;" : "=f"(r) : "f"(x));
    return r;
}

// ================= pass 1: convert K, K', V to fp16; compute beta =================
__global__ void __launch_bounds__(256)
preconvert(const float* __restrict__ kg, const float* __restrict__ vg)
{
    const int idx = blockIdx.x * 256 + threadIdx.x;   // 32768 rows
    const int r  = idx & 2047;
    const int bh = idx >> 11;
    const int b = bh >> 3, h = bh & 7;
    const float inv2 = 0.03125f;

    const float4* ks = (const float4*)(kg + ((size_t)(b * LLEN + r) * HH + h) * EE);
    __half2* kd = (__half2*)(g_Kh + ((size_t)bh * LLEN + r) * EE);
    #pragma unroll
    for (int i = 0; i < 8; i++) {
        float4 t = ks[i];
        kd[2*i]   = __floats2half2_rn(t.x, t.y);
        kd[2*i+1] = __floats2half2_rn(t.z, t.w);
    }
    const int rk = h * 256 + (r >> 3), hk = r & 7;     // scrambled reshape row
    const float4* kps = (const float4*)(kg + ((size_t)(b * LLEN + rk) * HH + hk) * EE);
    __half2* kpd = (__half2*)(g_Kph + ((size_t)bh * LLEN + r) * EE);
    float k2 = 0.f;
    #pragma unroll
    for (int i = 0; i < 8; i++) {
        float4 t = kps[i];
        k2 += t.x*t.x + t.y*t.y + t.z*t.z + t.w*t.w;
        kpd[2*i]   = __floats2half2_rn(t.x, t.y);
        kpd[2*i+1] = __floats2half2_rn(t.z, t.w);
    }
    g_beta[(size_t)bh * LLEN + r] = __expf(-k2 * inv2);

    const float4* vs = (const float4*)(vg + ((size_t)(b * LLEN + r) * HH + h) * DD);
    __half2* vh = (__half2*)(g_Vh + ((size_t)bh * LLEN + r) * DD);
    #pragma unroll
    for (int i = 0; i < 8; i++) {
        float4 t = vs[i];
        vh[2*i]   = __floats2half2_rn(t.x, t.y);
        vh[2*i+1] = __floats2half2_rn(t.z, t.w);
    }
}

// ================= main kernel =================
__global__ void __launch_bounds__(NTHR, 4)
gauss_attn_mma4(const float* __restrict__ qg, float* __restrict__ outg)
{
    extern __shared__ Tile tiles[];   // [2]
    const int tid  = threadIdx.x;
    const int lane = tid & 31;
    const int wid  = tid >> 5;
    const int g    = lane >> 2;
    const int tg   = lane & 3;
    const int i8   = lane & 7;
    const int g4lo = (lane >> 3) & 1;
    const int g4hi = lane >> 4;

    const int bx = blockIdx.x;
    const int u  = bx >> 4;
    const int lt = (u & 1) ? (u >> 1) : (31 - (u >> 1));   // interleaved heavy/light
    const int bh = bx & 15;
    const int b  = bh >> 3, h = bh & 7;
    const int l0 = lt * 64;
    const int nT = lt + 1;

    const float inv2 = 0.03125f;                   // 1/32
    const float inv3 = 0.005524271728019903f;      // 32^-1.5

    const int r0g = l0 + wid * 16 + g;
    const int r1g = r0g + 8;
    const int rmaxW = l0 + wid * 16 + 15;

    // ---- incremental gmem pointers for tile loads ----
    const int lr = tid >> 1, half = tid & 1;
    const size_t rowbase = ((size_t)bh * LLEN + lr) * EE + half * 16;
    const __half* kP  = g_Kh  + rowbase;
    const __half* kpP = g_Kph + rowbase;
    const __half* vhP = g_Vh  + rowbase;
    const float*  bP  = g_beta + (size_t)bh * LLEN + tid * 4;

    // issue tile 0 into buffer 0
    {
        Tile* tn = &tiles[0];
        cp16(smem_u32(&tn->K [lr][half*16]),   kP);
        cp16(smem_u32(&tn->K [lr][half*16+8]), kP  + 8);
        cp16(smem_u32(&tn->Kp[lr][half*16]),   kpP);
        cp16(smem_u32(&tn->Kp[lr][half*16+8]), kpP + 8);
        cp16(smem_u32(&tn->Vh[lr][half*16]),   vhP);
        cp16(smem_u32(&tn->Vh[lr][half*16+8]), vhP + 8);
        if (tid < 16) cp16(smem_u32(&tn->beta[tid*4]), bP);
    }
    CP_COMMIT();
    kP += 2048; kpP += 2048; vhP += 2048; bP += 64;

    // ---- Q / Q' fragments: load raw, compute q2 and alpha, then pack fp16 ----
    float2 qa[2][4], qp[2][4];
    float q2r0 = 0.f, q2r1 = 0.f;
    #pragma unroll
    for (int kk = 0; kk < 2; kk++) {
        const float* p0 = qg + ((size_t)(b * LLEN + r0g) * HH + h) * EE + 16 * kk + 2 * tg;
        const float* p1 = qg + ((size_t)(b * LLEN + r1g) * HH + h) * EE + 16 * kk + 2 * tg;
        qa[kk][0] = *(const float2*)p0;
        qa[kk][1] = *(const float2*)p1;
        qa[kk][2] = *(const float2*)(p0 + 8);
        qa[kk][3] = *(const float2*)(p1 + 8);

        const int lq0 = h * 256 + (r0g >> 3), hq0 = r0g & 7;
        const int lq1 = h * 256 + (r1g >> 3), hq1 = r1g & 7;
        const float* s0p = qg + ((size_t)(b * LLEN + lq0) * HH + hq0) * EE + 16 * kk + 2 * tg;
        const float* s1p = qg + ((size_t)(b * LLEN + lq1) * HH + hq1) * EE + 16 * kk + 2 * tg;
        qp[kk][0] = *(const float2*)s0p;
        qp[kk][1] = *(const float2*)s1p;
        qp[kk][2] = *(const float2*)(s0p + 8);
        qp[kk][3] = *(const float2*)(s1p + 8);
        q2r0 += qp[kk][0].x*qp[kk][0].x + qp[kk][0].y*qp[kk][0].y
              + qp[kk][2].x*qp[kk][2].x + qp[kk][2].y*qp[kk][2].y;
        q2r1 += qp[kk][1].x*qp[kk][1].x + qp[kk][1].y*qp[kk][1].y
              + qp[kk][3].x*qp[kk][3].x + qp[kk][3].y*qp[kk][3].y;
    }
    q2r0 += __shfl_xor_sync(0xffffffffu, q2r0, 1);
    q2r0 += __shfl_xor_sync(0xffffffffu, q2r0, 2);
    q2r1 += __shfl_xor_sync(0xffffffffu, q2r1, 1);
    q2r1 += __shfl_xor_sync(0xffffffffu, q2r1, 2);
    const float al0 = __expf(-q2r0 * inv2);        // alpha = exp(-||q'||^2/32)
    const float al1 = __expf(-q2r1 * inv2);

    const float sc0 = inv3 * L2E * al0;            // fold scale, log2e, alpha into Q
    const float sc1 = inv3 * L2E * al1;
    const float cs  = inv2 * 2.f * L2E;            // Q' scale: 2*log2e/32 folded

    uint32_t qA[2][4], pA_[2][4];
    #pragma unroll
    for (int kk = 0; kk < 2; kk++) {
        qA[kk][0] = pack2h(qa[kk][0].x * sc0, qa[kk][0].y * sc0);
        qA[kk][1] = pack2h(qa[kk][1].x * sc1, qa[kk][1].y * sc1);
        qA[kk][2] = pack2h(qa[kk][2].x * sc0, qa[kk][2].y * sc0);
        qA[kk][3] = pack2h(qa[kk][3].x * sc1, qa[kk][3].y * sc1);
        pA_[kk][0] = pack2h(qp[kk][0].x * cs, qp[kk][0].y * cs);
        pA_[kk][1] = pack2h(qp[kk][1].x * cs, qp[kk][1].y * cs);
        pA_[kk][2] = pack2h(qp[kk][2].x * cs, qp[kk][2].y * cs);
        pA_[kk][3] = pack2h(qp[kk][3].x * cs, qp[kk][3].y * cs);
    }
    const uint32_t ONESH = pack2h(1.f, 1.f);

    float4 O[4], O5;
    #pragma unroll
    for (int i = 0; i < 4; i++) O[i] = make_float4(0.f, 0.f, 0.f, 0.f);
    O5 = make_float4(0.f, 0.f, 0.f, 0.f);

    for (int t = 0; t < nT; t++) {
        const int cur = t & 1;
        CP_WAIT0();
        __syncthreads();
        if (t + 1 < nT) {
            Tile* tn = &tiles[cur ^ 1];
            cp16(smem_u32(&tn->K [lr][half*16]),   kP);
            cp16(smem_u32(&tn->K [lr][half*16+8]), kP  + 8);
            cp16(smem_u32(&tn->Kp[lr][half*16]),   kpP);
            cp16(smem_u32(&tn->Kp[lr][half*16+8]), kpP + 8);
            cp16(smem_u32(&tn->Vh[lr][half*16]),   vhP);
            cp16(smem_u32(&tn->Vh[lr][half*16+8]), vhP + 8);
            if (tid < 16) cp16(smem_u32(&tn->beta[tid*4]), bP);
            CP_COMMIT();
            kP += 2048; kpP += 2048; vhP += 2048; bP += 64;
        }
        Tile& tb = tiles[cur];
        const uint32_t kb  = smem_u32(&tb.K [0][0]);
        const uint32_t kpb = smem_u32(&tb.Kp[0][0]);
        const uint32_t vhb = smem_u32(&tb.Vh[0][0]);

        const int  s0    = t * 64;
        const bool maskT = (t == nT - 1);

        #pragma unroll
        for (int h2 = 0; h2 < 2; h2++) {
            if (s0 + h2 * 32 > rmaxW) continue;   // fully-masked half (warp-uniform)
            float4 S[4], C[4];
            #pragma unroll
            for (int i = 0; i < 4; i++) {
                S[i] = make_float4(0.f, 0.f, 0.f, 0.f);
                C[i] = make_float4(0.f, 0.f, 0.f, 0.f);
            }
            // ---- S' = L2E*alpha*scale*(Q K^T),  C' = 2*L2E/32*(Q' K'^T) ----
            #pragma unroll
            for (int p = 0; p < 2; p++) {
                const uint32_t rowoff = (uint32_t)(((h2 * 4 + p * 2 + g4hi) * 8 + i8) * 80);
                #pragma unroll
                for (int kk = 0; kk < 2; kk++) {
                    const uint32_t off = rowoff + kk * 32 + g4lo * 16;
                    uint32_t rB[4];
                    ldsm4(rB, kb + off);
                    mma16816(S[p*2],   qA[kk], rB[0], rB[1]);
                    mma16816(S[p*2+1], qA[kk], rB[2], rB[3]);
                    ldsm4(rB, kpb + off);
                    mma16816(C[p*2],   pA_[kk], rB[0], rB[1]);
                    mma16816(C[p*2+1], pA_[kk], rB[2], rB[3]);
                }
            }
            // ---- epilogue: p = 2^( S' * 2^(C') * beta ), pack fp16 ----
            uint32_t pAh[2][4];
            #pragma unroll
            for (int nt4 = 0; nt4 < 4; nt4++) {
                const int nt = h2 * 4 + nt4;
                const int cl = nt * 8 + 2 * tg;
                const float2 bb = *(const float2*)&tb.beta[cl];
                float px = ex2(S[nt4].x * ex2(C[nt4].x) * bb.x);
                float py = ex2(S[nt4].y * ex2(C[nt4].y) * bb.y);
                float pz = ex2(S[nt4].z * ex2(C[nt4].z) * bb.x);
                float pw = ex2(S[nt4].w * ex2(C[nt4].w) * bb.y);
                if (maskT) {
                    const int cg = s0 + cl;
                    if (cg     > r0g) px = 0.f;
                    if (cg + 1 > r0g) py = 0.f;
                    if (cg     > r1g) pz = 0.f;
                    if (cg + 1 > r1g) pw = 0.f;
                }
                const int j2 = nt4 >> 1;
                const int rr = (nt4 & 1) * 2;
                pAh[j2][rr]     = pack2h(px, py);
                pAh[j2][rr + 1] = pack2h(pz, pw);
            }
            // ---- O += P V ; row sums via ones-column MMA ----
            #pragma unroll
            for (int j2 = 0; j2 < 2; j2++) {
                const uint32_t srow = (uint32_t)((h2 * 32 + j2 * 16 + g4lo * 8 + i8) * 80);
                #pragma unroll
                for (int dp = 0; dp < 2; dp++) {
                    const uint32_t off = srow + (dp * 16 + g4hi * 8) * 2;
                    uint32_t vh[4];
                    ldsm4t(vh, vhb + off);
                    mma16816(O[dp*2],   pAh[j2], vh[0], vh[1]);
                    mma16816(O[dp*2+1], pAh[j2], vh[2], vh[3]);
                }
                mma16816(O5, pAh[j2], ONESH, ONESH);   // lsum accumulator
            }
        }
    }

    // ---- finalize: O5.x / O5.z are complete row sums (warp-collective) ----
    const float rl0 = 1.f / O5.x;
    const float rl1 = 1.f / O5.z;

    float* o0 = outg + ((size_t)(b * LLEN + r0g) * HH + h) * DD;
    float* o1 = outg + ((size_t)(b * LLEN + r1g) * HH + h) * DD;
    #pragma unroll
    for (int dt = 0; dt < 4; dt++) {
        const int col = dt * 8 + 2 * tg;
        *(float2*)(o0 + col) = make_float2(O[dt].x * rl0, O[dt].y * rl0);
        *(float2*)(o1 + col) = make_float2(O[dt].z * rl1, O[dt].w * rl1);
    }
}

extern "C" void kernel_launch(void* const* d_in, const int* in_sizes, int n_in,
                              void* d_out, int out_size)
{
    const float* q = (const float*)d_in[0];
    const float* k = (const float*)d_in[1];
    const float* v = (const float*)d_in[2];

    preconvert<<<128, 256>>>(k, v);

    cudaFuncSetAttribute(gauss_attn_mma4,
                         cudaFuncAttributeMaxDynamicSharedMemorySize, SMEM_BYTES);
    gauss_attn_mma4<<<512, NTHR, SMEM_BYTES>>>(q, (float*)d_out);
}